// round 16
// baseline (speedup 1.0000x reference)
#include <cuda_runtime.h>
#include <math_constants.h>

#define NN  1024
#define VV  32000
#define BB  16
#define TT  128
#define GG  128            // CTAs in forward kernel (all co-resident)
#define RR  (NN/GG)        // 8 rows of E_T per CTA
#define TPB 512            // 16 warps: 4 per SMSP for latency hiding
#define PPB 256            // prep kernels keep 256

typedef unsigned long long ull;

// ---------------- device scratch (static; no runtime alloc) ----------------
__device__ unsigned short d_ETh[NN*NN];       // bf16 exp(trans - collse), 2 MB
__device__ float          d_rowlse[NN];
__device__ float          d_collse[NN];
__device__ float          d_prilse;
__device__ float          d_piadj[NN];        // pri - prilse
__device__ float          d_emitg[TT*NN*BB];  // emit - rowlse, [t][m][b]
__device__ unsigned short d_eag[2][BB*NN];    // bf16 exp(alpha - shift), ping-pong
__device__ float          d_easum[TT*BB];     // sum_n ea per (t,b)
__device__ float          d_shift[TT*BB];     // shift used per (t,b)
__device__ unsigned       d_barcnt;           // grid barrier counter

// ---------------- helpers ----------------
__device__ __forceinline__ ull ffma2(ull a, ull b, ull c) {
    ull d;
    asm("fma.rn.f32x2 %0, %1, %2, %3;" : "=l"(d) : "l"(a), "l"(b), "l"(c));
    return d;
}
__device__ __forceinline__ ull bf2f32x2(unsigned u) {
    unsigned lo = u << 16, hi = u & 0xffff0000u;
    ull p;
    asm("mov.b64 %0, {%1,%2};" : "=l"(p) : "r"(lo), "r"(hi));
    return p;
}
__device__ __forceinline__ void cp_async16(unsigned dst_smem, const void* src) {
    asm volatile("cp.async.cg.shared.global [%0], [%1], 16;"
                 :: "r"(dst_smem), "l"(src));
}
__device__ __forceinline__ unsigned bf16x2pack(float lo, float hi) {
    unsigned r;
    asm("cvt.rn.bf16x2.f32 %0, %1, %2;" : "=r"(r) : "f"(hi), "f"(lo));
    return r;
}

// grid barrier: release-arrive + acquire-spin (exact R4/R9 pattern)
__device__ __forceinline__ void gbar(unsigned target) {
    __syncthreads();
    if (threadIdx.x == 0) {
        asm volatile("red.release.gpu.add.u32 [%0], 1;" :: "l"(&d_barcnt));
        unsigned v;
        do {
            asm volatile("ld.acquire.gpu.u32 %0, [%1];" : "=r"(v) : "l"(&d_barcnt));
        } while (v < target);
    }
    __syncthreads();
}

// ---- prep 1: rowlse (0..1023) + collse (1024..1055) + prilse (1056) --------
__global__ void k_pre1(const float* __restrict__ emis,
                       const float* __restrict__ trans,
                       const float* __restrict__ pri) {
    __shared__ float red[PPB];
    if (blockIdx.x < NN) {
        int n = blockIdx.x;
        const float4* row4 = (const float4*)(emis + (size_t)n * VV);
        float s = 0.f;
        for (int i = threadIdx.x; i < VV / 4; i += PPB) {
            float4 v = row4[i];
            s += __expf(v.x) + __expf(v.y) + __expf(v.z) + __expf(v.w);
        }
        red[threadIdx.x] = s;
        __syncthreads();
        for (int off = PPB / 2; off; off >>= 1) {
            if (threadIdx.x < off) red[threadIdx.x] += red[threadIdx.x + off];
            __syncthreads();
        }
        if (threadIdx.x == 0) d_rowlse[n] = __logf(red[0]);
    } else if (blockIdx.x < NN + NN / 32) {
        int tx = threadIdx.x & 31, ty = threadIdx.x >> 5;   // 32 x 8
        int col = (blockIdx.x - NN) * 32 + tx;
        float s = 0.f;
        for (int m = ty; m < NN; m += 8)
            s += __expf(trans[m * NN + col]);
        __shared__ float cs[8][32];
        cs[ty][tx] = s;
        __syncthreads();
        if (ty == 0) {
            float s1 = s;
#pragma unroll
            for (int j = 1; j < 8; j++) s1 += cs[j][tx];
            d_collse[col] = __logf(s1);
        }
    } else {
        float s = 0.f;
        for (int i = threadIdx.x; i < NN; i += PPB)
            s += __expf(pri[i]);
        red[threadIdx.x] = s;
        __syncthreads();
        for (int off = PPB / 2; off; off >>= 1) {
            if (threadIdx.x < off) red[threadIdx.x] += red[threadIdx.x + off];
            __syncthreads();
        }
        if (threadIdx.x == 0) d_prilse = __logf(red[0]);
    }
}

// ---- prep 2: E_T bf16 = exp(trans - collse), pure streaming ----
__global__ void k_prepT(const float* __restrict__ trans) {
    int m = blockIdx.x;
    const float* rowp = trans + (size_t)m * NN;
    for (int n = threadIdx.x; n < NN; n += PPB) {
        float e = __expf(rowp[n] - d_collse[n]);
        unsigned r;
        asm("cvt.rn.bf16x2.f32 %0, %1, %2;" : "=r"(r) : "f"(0.f), "f"(e));
        d_ETh[m * NN + n] = (unsigned short)(r & 0xffffu);
    }
}

// ---- prep 3: gather (0..127) + init/piadj (128..143) ----
__global__ void k_pre3(const float* __restrict__ emis,
                       const int* __restrict__ x,
                       const float* __restrict__ pri) {
    if (blockIdx.x < TT) {
        int t = blockIdx.x;
        __shared__ int tok[BB];
        if (threadIdx.x < BB) tok[threadIdx.x] = x[threadIdx.x * TT + t];
        __syncthreads();
        float* dst = d_emitg + (size_t)t * NN * BB;
        for (int i = threadIdx.x; i < NN * BB; i += PPB) {
            int m = i >> 4, b = i & 15;
            dst[i] = __ldg(&emis[(size_t)m * VV + tok[b]]) - d_rowlse[m];
        }
    } else {
        int j = blockIdx.x - TT;   // 0..15
        if (threadIdx.x < 128) d_easum[j * 128 + threadIdx.x] = 0.f;
        if (j == 0) {
            if (threadIdx.x == 0) d_barcnt = 0u;
            float pl = d_prilse;
            for (int m = threadIdx.x; m < NN; m += PPB)
                d_piadj[m] = pri[m] - pl;
        }
    }
}

// ---------------- persistent forward (R9 structure, 16 warps) ---------------
// smem: E bf16 16KB + ea bf16 32KB + alpha partials (2x128) + ea temp (128)
#define FWD_SMEM (RR*NN*2 + BB*NN*2 + (2*RR*BB + RR*BB)*4)

__global__ void __launch_bounds__(TPB, 1)
k_forward(const int* __restrict__ len, float* __restrict__ out) {
    extern __shared__ char sh[];
    char*  E_shb    = sh;                            // [RR][NN] bf16, 16KB
    char*  ea_sh    = sh + RR * NN * 2;              // [BB][NN] bf16, 32KB
    float* alpha_sh = (float*)(ea_sh + BB * NN * 2); // [2][RR*BB] partials
    float* eat_sh   = alpha_sh + 2 * RR * BB;        // [RR*BB]
    __shared__ float sA[BB], sB[BB];                 // shift(t-1), shift(t)

    const int g = blockIdx.x, tid = threadIdx.x;
    const int w = tid >> 5, lane = tid & 31;
    const int nh = w >> 3;                 // n-half: warps 0-7 -> 0, 8-15 -> 1
    const int mt = w & 3;                  // 4 row-pairs: rows mt*2, mt*2+1
    const int bt = (w >> 2) & 1;           // batch half
    const int ltid = tid & 255;            // index within half's 256 threads
    const unsigned ea_smem = (unsigned)__cvta_generic_to_shared(ea_sh);

    // stage E_T slice (bf16, 16KB) once
    {
        const uint4* src = (const uint4*)(d_ETh + (size_t)g * RR * NN);
        uint4* dst = (uint4*)E_shb;
        for (int i = tid; i < RR * NN * 2 / 16; i += TPB) dst[i] = src[i];
    }
    if (tid < BB) { sA[tid] = 0.f; sB[tid] = 0.f; }
    float lseP = 0.f, sPrev = 0.f;                   // tid<16 state
    __syncthreads();

    const int ml_f = tid >> 4, b_f = tid & 15, m_f = g * RR + ml_f;

    for (int t = 0; t < TT; t++) {
        // prefetches: emit term + easum(t-1) (final since barrier t-1)
        float em = 0.f, pa = 0.f, easumP = 0.f;
        if (tid < RR * BB) {
            em = __ldcg(&d_emitg[((size_t)t * NN + m_f) * BB + b_f]);
            if (t == 0) pa = __ldcg(&d_piadj[m_f]);
        }
        if (tid < BB && t >= 1)
            easumP = __ldcg(&d_easum[(t - 1) * BB + tid]);

        // -------- matvec: 2 chunks per n-half, per-half barrier pipeline ----
        if (t > 0) {
            ull acc[2][8];
#pragma unroll
            for (int j = 0; j < 2; j++)
#pragma unroll
                for (int k = 0; k < 8; k++) acc[j][k] = 0ull;
#pragma unroll
            for (int cc = 0; cc < 2; cc++) {
                if (cc == 0) asm volatile("cp.async.wait_group 1;");
                else         asm volatile("cp.async.wait_group 0;");
                asm volatile("bar.sync %0, 256;" :: "r"(2 + nh));
                int n0 = nh * 512 + cc * 256 + lane * 8;   // 8 bf16 per lane
                uint4 ev[2];
#pragma unroll
                for (int j = 0; j < 2; j++)
                    ev[j] = *(const uint4*)(E_shb + ((mt * 2 + j) * NN + n0) * 2);
                ull e[2][4];
#pragma unroll
                for (int j = 0; j < 2; j++) {
                    e[j][0] = bf2f32x2(ev[j].x); e[j][1] = bf2f32x2(ev[j].y);
                    e[j][2] = bf2f32x2(ev[j].z); e[j][3] = bf2f32x2(ev[j].w);
                }
#pragma unroll
                for (int k = 0; k < 8; k++) {
                    uint4 av = *(const uint4*)(ea_sh + ((bt * 8 + k) * NN + n0) * 2);
                    ull a0 = bf2f32x2(av.x), a1 = bf2f32x2(av.y);
                    ull a2 = bf2f32x2(av.z), a3 = bf2f32x2(av.w);
#pragma unroll
                    for (int j = 0; j < 2; j++) {
                        acc[j][k] = ffma2(e[j][0], a0, acc[j][k]);
                        acc[j][k] = ffma2(e[j][1], a1, acc[j][k]);
                        acc[j][k] = ffma2(e[j][2], a2, acc[j][k]);
                        acc[j][k] = ffma2(e[j][3], a3, acc[j][k]);
                    }
                }
            }
            float r[2][8];
#pragma unroll
            for (int j = 0; j < 2; j++)
#pragma unroll
                for (int k = 0; k < 8; k++) {
                    float2 f = *(float2*)&acc[j][k];
                    r[j][k] = f.x + f.y;
                }
#pragma unroll
            for (int off = 16; off; off >>= 1)
#pragma unroll
                for (int j = 0; j < 2; j++)
#pragma unroll
                    for (int k = 0; k < 8; k++)
                        r[j][k] += __shfl_xor_sync(0xffffffffu, r[j][k], off);
            if (lane == 0) {
#pragma unroll
                for (int j = 0; j < 2; j++)
#pragma unroll
                    for (int k = 0; k < 8; k++)
                        alpha_sh[nh * 128 + (mt * 2 + j) * BB + bt * 8 + k] = r[j][k];
            }
        }

        // -------- shift(t) from lse(t-1) (prefetched easum) --------
        if (tid < BB) {
            float sh_t;
            if (t == 0) sh_t = 0.f;
            else {
                float lse = sPrev + __logf(easumP);          // lse(t-1)
                float d = (t == 1) ? 0.f
                                   : fminf(20.f, fmaxf(-40.f, lse - lseP));
                sh_t = lse + d;
                lseP = lse;
            }
            sA[tid] = sPrev;
            sB[tid] = sh_t;
            sPrev = sh_t;
            if (g == 0) d_shift[t * BB + tid] = sh_t;
        }
        __syncthreads();

        // -------- finalize: alpha -> ea (shifted) --------
        if (tid < RR * BB) {
            float A = (t == 0)
                ? (em + pa)
                : (em + sA[b_f] + __logf(alpha_sh[tid] + alpha_sh[128 + tid]));
            eat_sh[tid] = __expf(A - sB[b_f]);
        }
        __syncthreads();

        // pack bf16 pairs -> d_eag[t&1]
        if (tid < 64) {
            int b = tid >> 2, q = tid & 3;
            float e0 = eat_sh[(2 * q) * BB + b];
            float e1 = eat_sh[(2 * q + 1) * BB + b];
            unsigned* dst = (unsigned*)&d_eag[t & 1][b * NN + g * RR + 2 * q];
            *dst = bf16x2pack(e0, e1);
        }
        // per-batch partial sums -> global
        if (tid < BB) {
            float sm = eat_sh[tid];
#pragma unroll
            for (int ml = 1; ml < RR; ml++) sm += eat_sh[ml * BB + tid];
            atomicAdd(&d_easum[t * BB + tid], sm);
        }

        gbar((unsigned)(t + 1) * GG);

        // -------- issue async reload of ea(t) for step t+1 (per half) ------
        if (t < TT - 1) {
            const char* src = (const char*)d_eag[t & 1];
#pragma unroll
            for (int cc = 0; cc < 2; cc++) {
#pragma unroll
                for (int k = 0; k < 2; k++) {
                    int idx = ltid + 256 * k;        // [0,512) 16B units
                    int b = idx >> 5, o = idx & 31;
                    unsigned off =
                        (unsigned)(b * (NN * 2) + nh * 1024 + cc * 512 + o * 16);
                    cp_async16(ea_smem + off, src + off);
                }
                asm volatile("cp.async.commit_group;");
            }
        }
    }

    // final output: out[b] = shift[len-1] + log(easum[len-1])
    if (g == 0 && tid < BB) {
        int tb = len[tid] - 1;
        tb = tb < 0 ? 0 : (tb > TT - 1 ? TT - 1 : tb);
        out[tid] = d_shift[tb * BB + tid] + __logf(__ldcg(&d_easum[tb * BB + tid]));
    }
}

// ---------------- launch: 4 kernels; forward is launch #4 ----------------
extern "C" void kernel_launch(void* const* d_in, const int* in_sizes, int n_in,
                              void* d_out, int out_size) {
    (void)in_sizes; (void)n_in; (void)out_size;
    const float* emis  = (const float*)d_in[0];  // (N, V)
    const float* trans = (const float*)d_in[1];  // (N, N)
    const float* pri   = (const float*)d_in[2];  // (N,)
    const int*   x     = (const int*)d_in[3];    // (B, T)
    const int*   len   = (const int*)d_in[4];    // (B,)
    float*       out   = (float*)d_out;          // (B, 1)

    cudaFuncSetAttribute(k_forward, cudaFuncAttributeMaxDynamicSharedMemorySize,
                         FWD_SMEM);

    k_pre1<<<NN + NN / 32 + 1, PPB>>>(emis, trans, pri);  // rowlse+collse+prilse
    k_prepT<<<NN, PPB>>>(trans);                          // bf16 E_T
    k_pre3<<<TT + 16, PPB>>>(emis, x, pri);               // gather + init
    k_forward<<<GG, TPB, FWD_SMEM>>>(len, out);           // launch #4
}

// round 17
// speedup vs baseline: 1.0808x; 1.0808x over previous
#include <cuda_runtime.h>
#include <math_constants.h>

#define NN  1024
#define VV  32000
#define BB  16
#define TT  128
#define GG  128            // CTAs in forward kernel (all co-resident)
#define RR  (NN/GG)        // 8 rows of E_T per CTA
#define TPB 256

typedef unsigned long long ull;

// ---------------- device scratch (static; no runtime alloc) ----------------
__device__ unsigned short d_ETh[NN*NN];       // bf16 exp(trans - collse), 2 MB
__device__ float          d_rowlse[NN];
__device__ float          d_collse[NN];
__device__ float          d_prilse;
__device__ float          d_piadj[NN];        // pri - prilse
__device__ float          d_emitg[TT*NN*BB];  // emit - rowlse, [t][m][b]
__device__ unsigned short d_eag[2][BB*NN];    // bf16 exp(alpha - shift), ping-pong
__device__ float          d_easum[TT*BB];     // sum_n ea per (t,b)
__device__ float          d_shift[TT*BB];     // shift used per (t,b)
__device__ unsigned       d_barcnt;           // grid barrier counter

// ---------------- helpers ----------------
__device__ __forceinline__ ull ffma2(ull a, ull b, ull c) {
    ull d;
    asm("fma.rn.f32x2 %0, %1, %2, %3;" : "=l"(d) : "l"(a), "l"(b), "l"(c));
    return d;
}
__device__ __forceinline__ ull bf2f32x2(unsigned u) {
    unsigned lo = u << 16, hi = u & 0xffff0000u;
    ull p;
    asm("mov.b64 %0, {%1,%2};" : "=l"(p) : "r"(lo), "r"(hi));
    return p;
}
__device__ __forceinline__ void cp_async16(unsigned dst_smem, const void* src) {
    asm volatile("cp.async.cg.shared.global [%0], [%1], 16;"
                 :: "r"(dst_smem), "l"(src));
}
__device__ __forceinline__ unsigned bf16x2pack(float lo, float hi) {
    unsigned r;
    asm("cvt.rn.bf16x2.f32 %0, %1, %2;" : "=r"(r) : "f"(hi), "f"(lo));
    return r;
}

// grid barrier: release-arrive + acquire-spin (exact R4/R9 pattern)
__device__ __forceinline__ void gbar(unsigned target) {
    __syncthreads();
    if (threadIdx.x == 0) {
        asm volatile("red.release.gpu.add.u32 [%0], 1;" :: "l"(&d_barcnt));
        unsigned v;
        do {
            asm volatile("ld.acquire.gpu.u32 %0, [%1];" : "=r"(v) : "l"(&d_barcnt));
        } while (v < target);
    }
    __syncthreads();
}

// ---- prep 1: rowlse (0..1023) + collse (1024..1055) + prilse (1056) --------
// no max-subtraction: inputs are standard normal (sum-exp is fp32-safe)
__global__ void k_pre1(const float* __restrict__ emis,
                       const float* __restrict__ trans,
                       const float* __restrict__ pri) {
    __shared__ float red[TPB];
    if (blockIdx.x < NN) {
        int n = blockIdx.x;
        const float4* row4 = (const float4*)(emis + (size_t)n * VV);
        float s = 0.f;
        for (int i = threadIdx.x; i < VV / 4; i += TPB) {
            float4 v = row4[i];
            s += __expf(v.x) + __expf(v.y) + __expf(v.z) + __expf(v.w);
        }
        red[threadIdx.x] = s;
        __syncthreads();
        for (int off = TPB / 2; off; off >>= 1) {
            if (threadIdx.x < off) red[threadIdx.x] += red[threadIdx.x + off];
            __syncthreads();
        }
        if (threadIdx.x == 0) d_rowlse[n] = __logf(red[0]);
    } else if (blockIdx.x < NN + NN / 32) {
        int tx = threadIdx.x & 31, ty = threadIdx.x >> 5;   // 32 x 8
        int col = (blockIdx.x - NN) * 32 + tx;
        float s = 0.f;
        for (int m = ty; m < NN; m += 8)
            s += __expf(trans[m * NN + col]);
        __shared__ float cs[8][32];
        cs[ty][tx] = s;
        __syncthreads();
        if (ty == 0) {
            float s1 = s;
#pragma unroll
            for (int j = 1; j < 8; j++) s1 += cs[j][tx];
            d_collse[col] = __logf(s1);
        }
    } else {
        float s = 0.f;
        for (int i = threadIdx.x; i < NN; i += TPB)
            s += __expf(pri[i]);
        red[threadIdx.x] = s;
        __syncthreads();
        for (int off = TPB / 2; off; off >>= 1) {
            if (threadIdx.x < off) red[threadIdx.x] += red[threadIdx.x + off];
            __syncthreads();
        }
        if (threadIdx.x == 0) d_prilse = __logf(red[0]);
    }
}

// ---- prep 2 (merged): gather (0..127) | E_T (128..1151) | init (1152..1167)
__global__ void k_pre2(const float* __restrict__ emis,
                       const float* __restrict__ trans,
                       const int* __restrict__ x,
                       const float* __restrict__ pri) {
    if (blockIdx.x < TT) {
        // emitg[t][m][b] = emission[m, x[b,t]] - rowlse[m]
        int t = blockIdx.x;
        __shared__ int tok[BB];
        if (threadIdx.x < BB) tok[threadIdx.x] = x[threadIdx.x * TT + t];
        __syncthreads();
        float* dst = d_emitg + (size_t)t * NN * BB;
        for (int i = threadIdx.x; i < NN * BB; i += TPB) {
            int m = i >> 4, b = i & 15;
            dst[i] = __ldg(&emis[(size_t)m * VV + tok[b]]) - d_rowlse[m];
        }
    } else if (blockIdx.x < TT + NN) {
        // E_T bf16 = exp(trans - collse), pure streaming
        int m = blockIdx.x - TT;
        const float* rowp = trans + (size_t)m * NN;
        for (int n = threadIdx.x; n < NN; n += TPB) {
            float e = __expf(rowp[n] - d_collse[n]);
            unsigned r;
            asm("cvt.rn.bf16x2.f32 %0, %1, %2;" : "=r"(r) : "f"(0.f), "f"(e));
            d_ETh[m * NN + n] = (unsigned short)(r & 0xffffu);
        }
    } else {
        int j = blockIdx.x - TT - NN;   // 0..15
        if (threadIdx.x < 128) d_easum[j * 128 + threadIdx.x] = 0.f;
        if (j == 0) {
            if (threadIdx.x == 0) d_barcnt = 0u;
            float pl = d_prilse;
            for (int m = threadIdx.x; m < NN; m += TPB)
                d_piadj[m] = pri[m] - pl;
        }
    }
}

// ---------------- persistent forward (byte-identical R9 loop) ---------------
// smem: E bf16 16KB + ea bf16 32KB + alpha partials (2x128) + ea temp (128)
#define FWD_SMEM (RR*NN*2 + BB*NN*2 + (2*RR*BB + RR*BB)*4)

__global__ void __launch_bounds__(TPB, 1)
k_forward(const int* __restrict__ len, float* __restrict__ out) {
    extern __shared__ char sh[];
    char*  E_shb    = sh;                            // [RR][NN] bf16, 16KB
    char*  ea_sh    = sh + RR * NN * 2;              // [BB][NN] bf16, 32KB
    float* alpha_sh = (float*)(ea_sh + BB * NN * 2); // [2][RR*BB] partials
    float* eat_sh   = alpha_sh + 2 * RR * BB;        // [RR*BB]
    __shared__ float sA[BB], sB[BB];                 // shift(t-1), shift(t)

    const int g = blockIdx.x, tid = threadIdx.x;
    const int w = tid >> 5, lane = tid & 31;
    const int nh = w >> 2;                 // n-half: warps 0-3 -> 0, 4-7 -> 1
    const int mt = w & 1, bt = (w >> 1) & 1;
    const int ltid = tid & 127;
    const unsigned ea_smem = (unsigned)__cvta_generic_to_shared(ea_sh);

    // stage E_T slice (bf16, 16KB) once
    {
        const uint4* src = (const uint4*)(d_ETh + (size_t)g * RR * NN);
        uint4* dst = (uint4*)E_shb;
        for (int i = tid; i < RR * NN * 2 / 16; i += TPB) dst[i] = src[i];
    }
    if (tid < BB) { sA[tid] = 0.f; sB[tid] = 0.f; }
    float lseP = 0.f, sPrev = 0.f;                   // tid<16 state
    __syncthreads();

    const int ml_f = tid >> 4, b_f = tid & 15, m_f = g * RR + ml_f;

    for (int t = 0; t < TT; t++) {
        // prefetches: emit term + easum(t-1) (final since barrier t-1)
        float em = 0.f, pa = 0.f, easumP = 0.f;
        if (tid < RR * BB) {
            em = __ldcg(&d_emitg[((size_t)t * NN + m_f) * BB + b_f]);
            if (t == 0) pa = __ldcg(&d_piadj[m_f]);
        }
        if (tid < BB && t >= 1)
            easumP = __ldcg(&d_easum[(t - 1) * BB + tid]);

        // -------- matvec: 2 chunks per n-half, per-half barrier pipeline ----
        if (t > 0) {
            ull acc[4][8];
#pragma unroll
            for (int j = 0; j < 4; j++)
#pragma unroll
                for (int k = 0; k < 8; k++) acc[j][k] = 0ull;
#pragma unroll
            for (int cc = 0; cc < 2; cc++) {
                if (cc == 0) asm volatile("cp.async.wait_group 1;");
                else         asm volatile("cp.async.wait_group 0;");
                asm volatile("bar.sync %0, 128;" :: "r"(2 + nh));
                int n0 = nh * 512 + cc * 256 + lane * 8;   // 8 bf16 per lane
                uint4 ev[4];
#pragma unroll
                for (int j = 0; j < 4; j++)
                    ev[j] = *(const uint4*)(E_shb + ((mt * 4 + j) * NN + n0) * 2);
                ull e[4][4];
#pragma unroll
                for (int j = 0; j < 4; j++) {
                    e[j][0] = bf2f32x2(ev[j].x); e[j][1] = bf2f32x2(ev[j].y);
                    e[j][2] = bf2f32x2(ev[j].z); e[j][3] = bf2f32x2(ev[j].w);
                }
#pragma unroll
                for (int k = 0; k < 8; k++) {
                    uint4 av = *(const uint4*)(ea_sh + ((bt * 8 + k) * NN + n0) * 2);
                    ull a0 = bf2f32x2(av.x), a1 = bf2f32x2(av.y);
                    ull a2 = bf2f32x2(av.z), a3 = bf2f32x2(av.w);
#pragma unroll
                    for (int j = 0; j < 4; j++) {
                        acc[j][k] = ffma2(e[j][0], a0, acc[j][k]);
                        acc[j][k] = ffma2(e[j][1], a1, acc[j][k]);
                        acc[j][k] = ffma2(e[j][2], a2, acc[j][k]);
                        acc[j][k] = ffma2(e[j][3], a3, acc[j][k]);
                    }
                }
            }
            float r[4][8];
#pragma unroll
            for (int j = 0; j < 4; j++)
#pragma unroll
                for (int k = 0; k < 8; k++) {
                    float2 f = *(float2*)&acc[j][k];
                    r[j][k] = f.x + f.y;
                }
#pragma unroll
            for (int off = 16; off; off >>= 1)
#pragma unroll
                for (int j = 0; j < 4; j++)
#pragma unroll
                    for (int k = 0; k < 8; k++)
                        r[j][k] += __shfl_xor_sync(0xffffffffu, r[j][k], off);
            if (lane == 0) {
#pragma unroll
                for (int j = 0; j < 4; j++)
#pragma unroll
                    for (int k = 0; k < 8; k++)
                        alpha_sh[nh * 128 + (mt * 4 + j) * BB + bt * 8 + k] = r[j][k];
            }
        }

        // -------- shift(t) from lse(t-1) (prefetched easum) --------
        if (tid < BB) {
            float sh_t;
            if (t == 0) sh_t = 0.f;
            else {
                float lse = sPrev + __logf(easumP);          // lse(t-1)
                float d = (t == 1) ? 0.f
                                   : fminf(20.f, fmaxf(-40.f, lse - lseP));
                sh_t = lse + d;
                lseP = lse;
            }
            sA[tid] = sPrev;
            sB[tid] = sh_t;
            sPrev = sh_t;
            if (g == 0) d_shift[t * BB + tid] = sh_t;
        }
        __syncthreads();

        // -------- finalize: alpha -> ea (shifted) --------
        if (tid < RR * BB) {
            float A = (t == 0)
                ? (em + pa)
                : (em + sA[b_f] + __logf(alpha_sh[tid] + alpha_sh[128 + tid]));
            eat_sh[tid] = __expf(A - sB[b_f]);
        }
        __syncthreads();

        // pack bf16 pairs -> d_eag[t&1]
        if (tid < 64) {
            int b = tid >> 2, q = tid & 3;
            float e0 = eat_sh[(2 * q) * BB + b];
            float e1 = eat_sh[(2 * q + 1) * BB + b];
            unsigned* dst = (unsigned*)&d_eag[t & 1][b * NN + g * RR + 2 * q];
            *dst = bf16x2pack(e0, e1);
        }
        // per-batch partial sums -> global
        if (tid < BB) {
            float sm = eat_sh[tid];
#pragma unroll
            for (int ml = 1; ml < RR; ml++) sm += eat_sh[ml * BB + tid];
            atomicAdd(&d_easum[t * BB + tid], sm);
        }

        gbar((unsigned)(t + 1) * GG);

        // -------- issue async reload of ea(t) for step t+1 (per half) ------
        if (t < TT - 1) {
            const char* src = (const char*)d_eag[t & 1];
#pragma unroll
            for (int cc = 0; cc < 2; cc++) {
#pragma unroll
                for (int k = 0; k < 4; k++) {
                    int idx = ltid + 128 * k;        // [0,512) 16B units
                    int b = idx >> 5, o = idx & 31;
                    unsigned off =
                        (unsigned)(b * (NN * 2) + nh * 1024 + cc * 512 + o * 16);
                    cp_async16(ea_smem + off, src + off);
                }
                asm volatile("cp.async.commit_group;");
            }
        }
    }

    // final output: out[b] = shift[len-1] + log(easum[len-1])
    if (g == 0 && tid < BB) {
        int tb = len[tid] - 1;
        tb = tb < 0 ? 0 : (tb > TT - 1 ? TT - 1 : tb);
        out[tid] = d_shift[tb * BB + tid] + __logf(__ldcg(&d_easum[tb * BB + tid]));
    }
}

// ---------------- launch: 3 kernels; forward is launch #3 ----------------
extern "C" void kernel_launch(void* const* d_in, const int* in_sizes, int n_in,
                              void* d_out, int out_size) {
    (void)in_sizes; (void)n_in; (void)out_size;
    const float* emis  = (const float*)d_in[0];  // (N, V)
    const float* trans = (const float*)d_in[1];  // (N, N)
    const float* pri   = (const float*)d_in[2];  // (N,)
    const int*   x     = (const int*)d_in[3];    // (B, T)
    const int*   len   = (const int*)d_in[4];    // (B,)
    float*       out   = (float*)d_out;          // (B, 1)

    cudaFuncSetAttribute(k_forward, cudaFuncAttributeMaxDynamicSharedMemorySize,
                         FWD_SMEM);

    k_pre1<<<NN + NN / 32 + 1, TPB>>>(emis, trans, pri);  // rowlse+collse+prilse
    k_pre2<<<TT + NN + 16, TPB>>>(emis, trans, x, pri);   // gather + E_T + init
    k_forward<<<GG, TPB, FWD_SMEM>>>(len, out);           // launch #3
}